// round 16
// baseline (speedup 1.0000x reference)
#include <cuda_runtime.h>
#include <cuda_fp16.h>
#include <cstdint>
#include <math.h>

#define BATCH   65536
#define KDIM    512
#define OUTA    256
#define HID     64
#define NB      1536            // packed B rows: 12 tiles of 128

// ---------------- scratch (static device globals) ------------------------
__device__ __half g_Bh[(size_t)NB * KDIM];       // main packed B (fp16)
__device__ __half g_Bc[(size_t)128 * KDIM];      // chooser B: Wc1|b1|b2|zeros
__device__ __half g_X[(size_t)BATCH * KDIM];     // x (fp16)
__device__ float  g_xb1[BATCH];
__device__ float  g_xb2[BATCH];
__device__ float2 g_sig[BATCH];                  // (s0, s1)
__device__ float  g_qpart[8][BATCH];             // q1: 0..3, q2: 4..7

// ======================= helpers ==========================================
__device__ __forceinline__ uint32_t smem_u32(const void* p) {
    uint32_t a;
    asm("{ .reg .u64 t; cvta.to.shared.u64 t, %1; cvt.u32.u64 %0, t; }" : "=r"(a) : "l"(p));
    return a;
}
#define CP_ASYNC16(dst, src) \
    asm volatile("cp.async.cg.shared.global [%0], [%1], 16;" :: "r"(dst), "l"(src))
#define CP_COMMIT() asm volatile("cp.async.commit_group;" ::: "memory")
#define CP_WAIT(n)  asm volatile("cp.async.wait_group %0;" :: "n"(n) : "memory")

__device__ __forceinline__ void ldmatrix_x4(uint32_t& r0, uint32_t& r1,
                                            uint32_t& r2, uint32_t& r3, uint32_t addr) {
    asm volatile("ldmatrix.sync.aligned.m8n8.x4.shared.b16 {%0,%1,%2,%3}, [%4];"
        : "=r"(r0), "=r"(r1), "=r"(r2), "=r"(r3) : "r"(addr));
}
__device__ __forceinline__ void mma_f16(float* c, const uint32_t* a, const uint32_t* b) {
    asm volatile(
        "mma.sync.aligned.m16n8k16.row.col.f32.f16.f16.f32 "
        "{%0,%1,%2,%3}, {%4,%5,%6,%7}, {%8,%9}, {%0,%1,%2,%3};"
        : "+f"(c[0]), "+f"(c[1]), "+f"(c[2]), "+f"(c[3])
        : "r"(a[0]), "r"(a[1]), "r"(a[2]), "r"(a[3]), "r"(b[0]), "r"(b[1]));
}

// ======================= pack kernel ======================================
// g_Bh rows: [0,512) = interleaved W1/W2 (2j=W1_j, 2j+1=W2_j)  -> tiles 0..3
//            [512,1024)=A1^T, [1024,1536)=A2^T                 -> tiles 4..11
// g_Bc rows: [0,64)=Wc1, 64=b1, 65=b2, [66,128)=0
__global__ __launch_bounds__(512) void pack_b_kernel(
    const float* __restrict__ W1, const float* __restrict__ W2,
    const float* __restrict__ Wc1,
    const float* __restrict__ b1, const float* __restrict__ b2,
    const float* __restrict__ A1, const float* __restrict__ A2)
{
    size_t idx = (size_t)blockIdx.x * blockDim.x + threadIdx.x;
    size_t total_main = (size_t)NB * KDIM;
    if (idx < total_main) {
        int row = (int)(idx >> 9);
        int k   = (int)(idx & 511);
        float v;
        if (row < 512) {
            int j = row >> 1;
            v = (row & 1) ? W2[(size_t)j * KDIM + k] : W1[(size_t)j * KDIM + k];
        }
        else if (row < 1024) v = A1[(size_t)k * KDIM + (row - 512)];
        else                 v = A2[(size_t)k * KDIM + (row - 1024)];
        g_Bh[idx] = __float2half_rn(v);
    } else {
        size_t cidx = idx - total_main;
        if (cidx >= (size_t)128 * KDIM) return;
        int row = (int)(cidx >> 9);
        int k   = (int)(cidx & 511);
        float v;
        if      (row < 64)   v = Wc1[(size_t)row * KDIM + k];
        else if (row == 64)  v = b1[k];
        else if (row == 65)  v = b2[k];
        else                 v = 0.f;
        g_Bc[cidx] = __float2half_rn(v);
    }
}

// ======================= chooser kernel ===================================
// R6 structure, fully unrolled with hoisted swizzled addresses.
#define CH_SMEM 32768

__global__ __launch_bounds__(256) void chooser_kernel(
    const float* __restrict__ x,
    const float* __restrict__ bc1,
    const float* __restrict__ Wc2, const float* __restrict__ bc2)
{
    extern __shared__ char smem[];
    const uint32_t sbase = smem_u32(smem);
    const uint32_t abase = sbase;
    const uint32_t bbase = sbase + 16384;
    const int tid   = threadIdx.x;
    const int wid   = tid >> 5;
    const int lane  = tid & 31;
    const int row0  = blockIdx.x * 128;

    const int warp_m = wid & 1;
    const int warp_n = wid >> 1;
    const int lq  = lane >> 2;
    const int lr  = lane & 3;
    const int t8  = lane >> 3;
    const int r8  = lane & 7;

    // hoisted B-load slots (4 per thread)
    int bld_row[4], bld_c[4];
    uint32_t bld_dst[4];
#pragma unroll
    for (int i = 0; i < 4; i++) {
        int lin = tid + i * 256;
        bld_row[i] = lin >> 3;
        bld_c[i]   = lin & 7;
        bld_dst[i] = bbase + bld_row[i] * 128 + ((bld_c[i] ^ (bld_row[i] & 7)) << 4);
    }
    // hoisted A-load slots (8 per thread)
    int ald_row[8], ald_f4[8];
    uint32_t ald_dst[8];
#pragma unroll
    for (int i = 0; i < 8; i++) {
        int lin = tid + i * 256;
        ald_row[i] = lin >> 4;
        ald_f4[i]  = lin & 15;
        int c   = ald_f4[i] >> 1;
        int sub = ald_f4[i] & 1;
        ald_dst[i] = ald_row[i] * 128 + ((c ^ (ald_row[i] & 7)) << 4) + sub * 8;
    }
    // hoisted LDSM row bases
    const int a_swz[4] = {
        warp_m * 64 + 0 * 16 + ((t8 & 1) << 3) + r8,
        warp_m * 64 + 1 * 16 + ((t8 & 1) << 3) + r8,
        warp_m * 64 + 2 * 16 + ((t8 & 1) << 3) + r8,
        warp_m * 64 + 3 * 16 + ((t8 & 1) << 3) + r8 };
    const int b_swz[2] = {
        warp_n * 32 + 0 * 16 + ((t8 >> 1) << 3) + r8,
        warp_n * 32 + 1 * 16 + ((t8 >> 1) << 3) + r8 };

    float acc[4][4][4];
#pragma unroll
    for (int mt = 0; mt < 4; mt++)
#pragma unroll
        for (int nt = 0; nt < 4; nt++)
#pragma unroll
            for (int i = 0; i < 4; i++) acc[mt][nt][i] = 0.f;

#pragma unroll
    for (int ck = 0; ck < 8; ck++) {
        const int k0 = ck * 64;
        __syncthreads();

#pragma unroll
        for (int i = 0; i < 4; i++) {
            const __half* src = g_Bc + (size_t)bld_row[i] * KDIM + k0 + bld_c[i] * 8;
            CP_ASYNC16(bld_dst[i], src);
        }
        CP_COMMIT();

#pragma unroll
        for (int i = 0; i < 8; i++) {
            float4 v = __ldg((const float4*)(x + (size_t)(row0 + ald_row[i]) * KDIM + k0) + ald_f4[i]);
            __half2 h0 = __floats2half2_rn(v.x, v.y);
            __half2 h1 = __floats2half2_rn(v.z, v.w);
            uint2 u;
            u.x = *(uint32_t*)&h0;
            u.y = *(uint32_t*)&h1;
            ((uint2*)(g_X + (size_t)(row0 + ald_row[i]) * KDIM + k0))[ald_f4[i]] = u;
            *(uint2*)(smem + ald_dst[i]) = u;
        }
        CP_WAIT(0);
        __syncthreads();

#pragma unroll
        for (int kk = 0; kk < 4; kk++) {
            uint32_t af[4][4];
#pragma unroll
            for (int mt = 0; mt < 4; mt++) {
                int ac = kk * 2 + (t8 >> 1);
                uint32_t addr = abase + a_swz[mt] * 128 + ((ac ^ (a_swz[mt] & 7)) << 4);
                ldmatrix_x4(af[mt][0], af[mt][1], af[mt][2], af[mt][3], addr);
            }
            uint32_t bf[4][2];
#pragma unroll
            for (int nt2 = 0; nt2 < 2; nt2++) {
                int bc = kk * 2 + (t8 & 1);
                uint32_t addr = bbase + b_swz[nt2] * 128 + ((bc ^ (b_swz[nt2] & 7)) << 4);
                ldmatrix_x4(bf[nt2 * 2][0], bf[nt2 * 2][1],
                            bf[nt2 * 2 + 1][0], bf[nt2 * 2 + 1][1], addr);
            }
#pragma unroll
            for (int mt = 0; mt < 4; mt++)
#pragma unroll
                for (int nt = 0; nt < 4; nt++)
                    mma_f16(acc[mt][nt], af[mt], bf[nt]);
        }
    }
    __syncthreads();

    float* red = (float*)smem;
    if (warp_n < 2) {
        float p0[4][2], p1[4][2];
#pragma unroll
        for (int mt = 0; mt < 4; mt++)
#pragma unroll
            for (int h = 0; h < 2; h++) { p0[mt][h] = 0.f; p1[mt][h] = 0.f; }
#pragma unroll
        for (int mt = 0; mt < 4; mt++) {
#pragma unroll
            for (int nt = 0; nt < 4; nt++) {
                const int c0 = warp_n * 32 + nt * 8 + 2 * lr;
                const float w00 = __ldg(&Wc2[c0]),      w01 = __ldg(&Wc2[c0 + 1]);
                const float w10 = __ldg(&Wc2[64 + c0]), w11 = __ldg(&Wc2[64 + c0 + 1]);
                const float bb0 = __ldg(&bc1[c0]),      bb1 = __ldg(&bc1[c0 + 1]);
                float hA0 = fmaxf(acc[mt][nt][0] + bb0, 0.f);
                float hA1 = fmaxf(acc[mt][nt][1] + bb1, 0.f);
                float hB0 = fmaxf(acc[mt][nt][2] + bb0, 0.f);
                float hB1 = fmaxf(acc[mt][nt][3] + bb1, 0.f);
                p0[mt][0] = fmaf(hA0, w00, fmaf(hA1, w01, p0[mt][0]));
                p1[mt][0] = fmaf(hA0, w10, fmaf(hA1, w11, p1[mt][0]));
                p0[mt][1] = fmaf(hB0, w00, fmaf(hB1, w01, p0[mt][1]));
                p1[mt][1] = fmaf(hB0, w10, fmaf(hB1, w11, p1[mt][1]));
            }
        }
#pragma unroll
        for (int mt = 0; mt < 4; mt++) {
#pragma unroll
            for (int h = 0; h < 2; h++) {
                p0[mt][h] += __shfl_xor_sync(0xffffffffu, p0[mt][h], 1);
                p0[mt][h] += __shfl_xor_sync(0xffffffffu, p0[mt][h], 2);
                p1[mt][h] += __shfl_xor_sync(0xffffffffu, p1[mt][h], 1);
                p1[mt][h] += __shfl_xor_sync(0xffffffffu, p1[mt][h], 2);
            }
        }
        if (lr == 0) {
#pragma unroll
            for (int mt = 0; mt < 4; mt++) {
                const int rl = warp_m * 64 + mt * 16 + lq;
                red[(rl * 2 + warp_n) * 2 + 0]       = p0[mt][0];
                red[(rl * 2 + warp_n) * 2 + 1]       = p1[mt][0];
                red[((rl + 8) * 2 + warp_n) * 2 + 0] = p0[mt][1];
                red[((rl + 8) * 2 + warp_n) * 2 + 1] = p1[mt][1];
            }
        }
    } else if (warp_n == 2 && lr == 0) {
#pragma unroll
        for (int mt = 0; mt < 4; mt++) {
            const int rA = row0 + warp_m * 64 + mt * 16 + lq;
            g_xb1[rA]     = acc[mt][0][0];
            g_xb2[rA]     = acc[mt][0][1];
            g_xb1[rA + 8] = acc[mt][0][2];
            g_xb2[rA + 8] = acc[mt][0][3];
        }
    }
    __syncthreads();

    if (tid < 128) {
        float l0 = red[(tid * 2 + 0) * 2 + 0] + red[(tid * 2 + 1) * 2 + 0] + __ldg(&bc2[0]);
        float l1 = red[(tid * 2 + 0) * 2 + 1] + red[(tid * 2 + 1) * 2 + 1] + __ldg(&bc2[1]);
        float s0 = 1.f / (1.f + expf(-l0));
        float s1 = 1.f / (1.f + expf(-l1));
        g_sig[row0 + tid] = make_float2(s0, s1);
    }
}

// ======================= fp16 mma.sync GEMM (exact R15) ===================
// CTA tile 128x128, 4 warps of 64x64, 128 threads, K-chunk 64,
// 3-stage cp.async pipeline, 2 CTAs/SM.  Main loop fully unrolled.
#define STAGE_BYTES 32768
#define SMEM_BYTES  (3 * STAGE_BYTES)     // 98304

__global__ __launch_bounds__(128, 2) void gemm_tc_kernel(float* __restrict__ out)
{
    extern __shared__ char smem[];
    const uint32_t sbase = smem_u32(smem);
    const int tid   = threadIdx.x;
    const int wid   = tid >> 5;               // 0..3
    const int lane  = tid & 31;
    const int bx    = blockIdx.x;             // 0..11
    const int row0  = blockIdx.y * 128;
    const int colbase = bx * 128;

    const int warp_m = wid & 1;               // 2 row groups of 64
    const int warp_n = wid >> 1;              // 2 col groups of 64
    const int lq  = lane >> 2;
    const int lr  = lane & 3;
    const int t8  = lane >> 3;
    const int r8  = lane & 7;

    const int a_swz[4] = {
        warp_m * 64 + 0 * 16 + ((t8 & 1) << 3) + r8,
        warp_m * 64 + 1 * 16 + ((t8 & 1) << 3) + r8,
        warp_m * 64 + 2 * 16 + ((t8 & 1) << 3) + r8,
        warp_m * 64 + 3 * 16 + ((t8 & 1) << 3) + r8 };
    const int b_swz[4] = {
        warp_n * 64 + 0 * 16 + ((t8 >> 1) << 3) + r8,
        warp_n * 64 + 1 * 16 + ((t8 >> 1) << 3) + r8,
        warp_n * 64 + 2 * 16 + ((t8 >> 1) << 3) + r8,
        warp_n * 64 + 3 * 16 + ((t8 >> 1) << 3) + r8 };

    int ld_row[8], ld_c[8];
    uint32_t ld_dst[8];
#pragma unroll
    for (int i = 0; i < 8; i++) {
        int lin = tid + i * 128;
        ld_row[i] = lin >> 3;
        ld_c[i]   = lin & 7;
        ld_dst[i] = ld_row[i] * 128 + ((ld_c[i] ^ (ld_row[i] & 7)) << 4);
    }

    auto load_chunk = [&](int stage, int k0) {
        uint32_t ab = sbase + stage * STAGE_BYTES;
        uint32_t bb = ab + 16384;
#pragma unroll
        for (int i = 0; i < 8; i++) {
            const __half* src = g_X + (size_t)(row0 + ld_row[i]) * KDIM + k0 + ld_c[i] * 8;
            CP_ASYNC16(ab + ld_dst[i], src);
        }
#pragma unroll
        for (int i = 0; i < 8; i++) {
            const __half* src = g_Bh + (size_t)(colbase + ld_row[i]) * KDIM + k0 + ld_c[i] * 8;
            CP_ASYNC16(bb + ld_dst[i], src);
        }
    };

    float acc[4][8][4];
#pragma unroll
    for (int mt = 0; mt < 4; mt++)
#pragma unroll
        for (int nt = 0; nt < 8; nt++)
#pragma unroll
            for (int i = 0; i < 4; i++) acc[mt][nt][i] = 0.f;

    load_chunk(0, 0);  CP_COMMIT();
    load_chunk(1, 64); CP_COMMIT();

#pragma unroll
    for (int ch = 0; ch < 8; ch++) {
        const int stage = ch % 3;
        if (ch + 2 < 8) { load_chunk((ch + 2) % 3, (ch + 2) * 64); CP_COMMIT(); }
        if (ch < 6)       CP_WAIT(2);
        else if (ch == 6) CP_WAIT(1);
        else              CP_WAIT(0);
        __syncthreads();

        const uint32_t ab = sbase + stage * STAGE_BYTES;
        const uint32_t bb = ab + 16384;

#pragma unroll
        for (int kk = 0; kk < 4; kk++) {
            uint32_t af[4][4];
#pragma unroll
            for (int mt = 0; mt < 4; mt++) {
                int ac = kk * 2 + (t8 >> 1);
                uint32_t addr = ab + a_swz[mt] * 128 + ((ac ^ (a_swz[mt] & 7)) << 4);
                ldmatrix_x4(af[mt][0], af[mt][1], af[mt][2], af[mt][3], addr);
            }
            uint32_t bf[8][2];
#pragma unroll
            for (int nt2 = 0; nt2 < 4; nt2++) {
                int bc = kk * 2 + (t8 & 1);
                uint32_t addr = bb + b_swz[nt2] * 128 + ((bc ^ (b_swz[nt2] & 7)) << 4);
                ldmatrix_x4(bf[nt2 * 2][0], bf[nt2 * 2][1],
                            bf[nt2 * 2 + 1][0], bf[nt2 * 2 + 1][1], addr);
            }
#pragma unroll
            for (int mt = 0; mt < 4; mt++)
#pragma unroll
                for (int nt = 0; nt < 8; nt++)
                    mma_f16(acc[mt][nt], af[mt], bf[nt]);
        }
        __syncthreads();
    }

    // =================== fused epilogue ===================================
    if (bx < 4) {
        // interleaved W1/W2: actor col = warp_n*32 + nt*4 + lr
#pragma unroll
        for (int mt = 0; mt < 4; mt++) {
            const int rA = row0 + warp_m * 64 + mt * 16 + lq;
            const float2 sA = __ldg(&g_sig[rA]);
            const float2 sB = __ldg(&g_sig[rA + 8]);
#pragma unroll
            for (int nt = 0; nt < 8; nt++) {
                const int col = bx * 64 + warp_n * 32 + nt * 4 + lr;
                out[(size_t)rA * OUTA + col] =
                    fmaf(sA.x, acc[mt][nt][0], sA.y * acc[mt][nt][1]);
                out[(size_t)(rA + 8) * OUTA + col] =
                    fmaf(sB.x, acc[mt][nt][2], sB.y * acc[mt][nt][3]);
            }
        }
    } else {
        // quadratic tiles: fused row-dot with fp16 x
        const int qt = bx - 4;                          // 0..7
        const int jbase = (qt < 4 ? qt : qt - 4) * 128;
        float p[4][2];
#pragma unroll
        for (int mt = 0; mt < 4; mt++) { p[mt][0] = 0.f; p[mt][1] = 0.f; }
#pragma unroll
        for (int mt = 0; mt < 4; mt++) {
            const int rA = row0 + warp_m * 64 + mt * 16 + lq;
#pragma unroll
            for (int nt = 0; nt < 8; nt++) {
                const int j = jbase + warp_n * 64 + nt * 8 + 2 * lr;
                const __half2 h0 = __ldg((const __half2*)(g_X + (size_t)rA * KDIM + j));
                const __half2 h1 = __ldg((const __half2*)(g_X + (size_t)(rA + 8) * KDIM + j));
                const float2 x0 = __half22float2(h0);
                const float2 x1 = __half22float2(h1);
                p[mt][0] = fmaf(acc[mt][nt][0], x0.x, fmaf(acc[mt][nt][1], x0.y, p[mt][0]));
                p[mt][1] = fmaf(acc[mt][nt][2], x1.x, fmaf(acc[mt][nt][3], x1.y, p[mt][1]));
            }
        }
#pragma unroll
        for (int mt = 0; mt < 4; mt++) {
#pragma unroll
            for (int h = 0; h < 2; h++) {
                p[mt][h] += __shfl_xor_sync(0xffffffffu, p[mt][h], 1);
                p[mt][h] += __shfl_xor_sync(0xffffffffu, p[mt][h], 2);
            }
        }
        __syncthreads();
        float* red = (float*)smem;                      // [128][2]
        if (lr == 0) {
#pragma unroll
            for (int mt = 0; mt < 4; mt++) {
                const int rl = warp_m * 64 + mt * 16 + lq;
                red[rl * 2 + warp_n]       = p[mt][0];
                red[(rl + 8) * 2 + warp_n] = p[mt][1];
            }
        }
        __syncthreads();
        g_qpart[qt][row0 + tid] = red[tid * 2] + red[tid * 2 + 1];
    }
}

// ======================= critic kernel ====================================
__global__ __launch_bounds__(256) void critic_kernel(
    const float* __restrict__ c1, const float* __restrict__ c2,
    float* __restrict__ out)
{
    const int r = blockIdx.x * 256 + threadIdx.x;
    float q1 = g_qpart[0][r] + g_qpart[1][r] + g_qpart[2][r] + g_qpart[3][r]
             + g_xb1[r] + c1[0];
    float q2 = g_qpart[4][r] + g_qpart[5][r] + g_qpart[6][r] + g_qpart[7][r]
             + g_xb2[r] + c2[0];
    float2 s = g_sig[r];
    out[(size_t)BATCH * OUTA + r] = s.x * q1 + s.y * q2;
}

// =========================================================================
extern "C" void kernel_launch(void* const* d_in, const int* in_sizes, int n_in,
                              void* d_out, int out_size)
{
    const float* x   = (const float*)d_in[0];
    const float* W1  = (const float*)d_in[1];
    const float* W2  = (const float*)d_in[2];
    const float* A1  = (const float*)d_in[3];
    const float* b1  = (const float*)d_in[4];
    const float* c1  = (const float*)d_in[5];
    const float* A2  = (const float*)d_in[6];
    const float* b2  = (const float*)d_in[7];
    const float* c2  = (const float*)d_in[8];
    const float* Wc1 = (const float*)d_in[9];
    const float* bc1 = (const float*)d_in[10];
    const float* Wc2 = (const float*)d_in[11];
    const float* bc2 = (const float*)d_in[12];
    float* out = (float*)d_out;

    cudaFuncSetAttribute(gemm_tc_kernel,
                         cudaFuncAttributeMaxDynamicSharedMemorySize, SMEM_BYTES);

    pack_b_kernel<<<((NB + 128) * KDIM + 511) / 512, 512>>>(W1, W2, Wc1, b1, b2, A1, A2);
    chooser_kernel<<<BATCH / 128, 256, CH_SMEM>>>(x, bc1, Wc2, bc2);
    gemm_tc_kernel<<<dim3(12, BATCH / 128), 128, SMEM_BYTES>>>(out);
    critic_kernel<<<BATCH / 256, 256>>>(c1, c2, out);
}

// round 17
// speedup vs baseline: 1.0608x; 1.0608x over previous
#include <cuda_runtime.h>
#include <cuda_fp16.h>
#include <cstdint>
#include <math.h>

#define BATCH   65536
#define KDIM    512
#define OUTA    256
#define HID     64
#define NB      1536            // packed B rows: 12 tiles of 128

// ---------------- scratch (static device globals) ------------------------
__device__ __half g_Bh[(size_t)NB * KDIM];       // main packed B (fp16)
__device__ __half g_Bc[(size_t)128 * KDIM];      // chooser B: Wc1|b1|b2|zeros
__device__ __half g_X[(size_t)BATCH * KDIM];     // x (fp16)
__device__ float  g_xb1[BATCH];
__device__ float  g_xb2[BATCH];
__device__ float2 g_sig[BATCH];                  // (s0, s1)
__device__ float  g_qpart[8][BATCH];             // q1: 0..3, q2: 4..7

// ======================= helpers ==========================================
__device__ __forceinline__ uint32_t smem_u32(const void* p) {
    uint32_t a;
    asm("{ .reg .u64 t; cvta.to.shared.u64 t, %1; cvt.u32.u64 %0, t; }" : "=r"(a) : "l"(p));
    return a;
}
#define CP_ASYNC16(dst, src) \
    asm volatile("cp.async.cg.shared.global [%0], [%1], 16;" :: "r"(dst), "l"(src))
#define CP_COMMIT() asm volatile("cp.async.commit_group;" ::: "memory")
#define CP_WAIT(n)  asm volatile("cp.async.wait_group %0;" :: "n"(n) : "memory")

__device__ __forceinline__ void ldmatrix_x4(uint32_t& r0, uint32_t& r1,
                                            uint32_t& r2, uint32_t& r3, uint32_t addr) {
    asm volatile("ldmatrix.sync.aligned.m8n8.x4.shared.b16 {%0,%1,%2,%3}, [%4];"
        : "=r"(r0), "=r"(r1), "=r"(r2), "=r"(r3) : "r"(addr));
}
__device__ __forceinline__ void mma_f16(float* c, const uint32_t* a, const uint32_t* b) {
    asm volatile(
        "mma.sync.aligned.m16n8k16.row.col.f32.f16.f16.f32 "
        "{%0,%1,%2,%3}, {%4,%5,%6,%7}, {%8,%9}, {%0,%1,%2,%3};"
        : "+f"(c[0]), "+f"(c[1]), "+f"(c[2]), "+f"(c[3])
        : "r"(a[0]), "r"(a[1]), "r"(a[2]), "r"(a[3]), "r"(b[0]), "r"(b[1]));
}

// ======================= pack kernel ======================================
// g_Bh rows: [0,512) = interleaved W1/W2 (2j=W1_j, 2j+1=W2_j)  -> tiles 0..3
//            [512,1024)=A1^T, [1024,1536)=A2^T                 -> tiles 4..11
// g_Bc rows: [0,64)=Wc1, 64=b1, 65=b2, [66,128)=0
__global__ __launch_bounds__(512) void pack_b_kernel(
    const float* __restrict__ W1, const float* __restrict__ W2,
    const float* __restrict__ Wc1,
    const float* __restrict__ b1, const float* __restrict__ b2,
    const float* __restrict__ A1, const float* __restrict__ A2)
{
    size_t idx = (size_t)blockIdx.x * blockDim.x + threadIdx.x;
    size_t total_main = (size_t)NB * KDIM;
    if (idx < total_main) {
        int row = (int)(idx >> 9);
        int k   = (int)(idx & 511);
        float v;
        if (row < 512) {
            int j = row >> 1;
            v = (row & 1) ? W2[(size_t)j * KDIM + k] : W1[(size_t)j * KDIM + k];
        }
        else if (row < 1024) v = A1[(size_t)k * KDIM + (row - 512)];
        else                 v = A2[(size_t)k * KDIM + (row - 1024)];
        g_Bh[idx] = __float2half_rn(v);
    } else {
        size_t cidx = idx - total_main;
        if (cidx >= (size_t)128 * KDIM) return;
        int row = (int)(cidx >> 9);
        int k   = (int)(cidx & 511);
        float v;
        if      (row < 64)   v = Wc1[(size_t)row * KDIM + k];
        else if (row == 64)  v = b1[k];
        else if (row == 65)  v = b2[k];
        else                 v = 0.f;
        g_Bc[cidx] = __float2half_rn(v);
    }
}

// ======================= chooser kernel (exact R6) ========================
#define CH_SMEM 32768

__global__ __launch_bounds__(256) void chooser_kernel(
    const float* __restrict__ x,
    const float* __restrict__ bc1,
    const float* __restrict__ Wc2, const float* __restrict__ bc2)
{
    extern __shared__ char smem[];
    const uint32_t sbase = smem_u32(smem);
    const uint32_t abase = sbase;
    const uint32_t bbase = sbase + 16384;
    const int tid   = threadIdx.x;
    const int wid   = tid >> 5;
    const int lane  = tid & 31;
    const int row0  = blockIdx.x * 128;

    const int warp_m = wid & 1;
    const int warp_n = wid >> 1;
    const int lq  = lane >> 2;
    const int lr  = lane & 3;
    const int t8  = lane >> 3;
    const int r8  = lane & 7;

    float acc[4][4][4];
#pragma unroll
    for (int mt = 0; mt < 4; mt++)
#pragma unroll
        for (int nt = 0; nt < 4; nt++)
#pragma unroll
            for (int i = 0; i < 4; i++) acc[mt][nt][i] = 0.f;

    for (int ck = 0; ck < 8; ck++) {
        const int k0 = ck * 64;
        __syncthreads();

#pragma unroll
        for (int i = 0; i < 4; i++) {
            int lin = tid + i * 256;
            int row = lin >> 3;
            int c   = lin & 7;
            const __half* src = g_Bc + (size_t)row * KDIM + k0 + c * 8;
            CP_ASYNC16(bbase + row * 128 + ((c ^ (row & 7)) << 4), src);
        }
        CP_COMMIT();

#pragma unroll
        for (int i = 0; i < 8; i++) {
            int lin = tid + i * 256;
            int row = lin >> 4;
            int f4  = lin & 15;
            float4 v = __ldg((const float4*)(x + (size_t)(row0 + row) * KDIM + k0) + f4);
            __half2 h0 = __floats2half2_rn(v.x, v.y);
            __half2 h1 = __floats2half2_rn(v.z, v.w);
            uint2 u;
            u.x = *(uint32_t*)&h0;
            u.y = *(uint32_t*)&h1;
            ((uint2*)(g_X + (size_t)(row0 + row) * KDIM + k0))[f4] = u;
            int c   = f4 >> 1;
            int sub = f4 & 1;
            *(uint2*)(smem + row * 128 + ((c ^ (row & 7)) << 4) + sub * 8) = u;
        }
        CP_WAIT(0);
        __syncthreads();

#pragma unroll
        for (int kk = 0; kk < 4; kk++) {
            uint32_t af[4][4];
#pragma unroll
            for (int mt = 0; mt < 4; mt++) {
                int arow = warp_m * 64 + mt * 16 + ((t8 & 1) << 3) + r8;
                int ac   = kk * 2 + (t8 >> 1);
                uint32_t addr = abase + arow * 128 + ((ac ^ (arow & 7)) << 4);
                ldmatrix_x4(af[mt][0], af[mt][1], af[mt][2], af[mt][3], addr);
            }
            uint32_t bf[4][2];
#pragma unroll
            for (int nt2 = 0; nt2 < 2; nt2++) {
                int brow = warp_n * 32 + nt2 * 16 + ((t8 >> 1) << 3) + r8;
                int bc   = kk * 2 + (t8 & 1);
                uint32_t addr = bbase + brow * 128 + ((bc ^ (brow & 7)) << 4);
                ldmatrix_x4(bf[nt2 * 2][0], bf[nt2 * 2][1],
                            bf[nt2 * 2 + 1][0], bf[nt2 * 2 + 1][1], addr);
            }
#pragma unroll
            for (int mt = 0; mt < 4; mt++)
#pragma unroll
                for (int nt = 0; nt < 4; nt++)
                    mma_f16(acc[mt][nt], af[mt], bf[nt]);
        }
    }
    __syncthreads();

    float* red = (float*)smem;
    if (warp_n < 2) {
        float p0[4][2], p1[4][2];
#pragma unroll
        for (int mt = 0; mt < 4; mt++)
#pragma unroll
            for (int h = 0; h < 2; h++) { p0[mt][h] = 0.f; p1[mt][h] = 0.f; }
#pragma unroll
        for (int mt = 0; mt < 4; mt++) {
#pragma unroll
            for (int nt = 0; nt < 4; nt++) {
                const int c0 = warp_n * 32 + nt * 8 + 2 * lr;
                const float w00 = __ldg(&Wc2[c0]),      w01 = __ldg(&Wc2[c0 + 1]);
                const float w10 = __ldg(&Wc2[64 + c0]), w11 = __ldg(&Wc2[64 + c0 + 1]);
                const float bb0 = __ldg(&bc1[c0]),      bb1 = __ldg(&bc1[c0 + 1]);
                float hA0 = fmaxf(acc[mt][nt][0] + bb0, 0.f);
                float hA1 = fmaxf(acc[mt][nt][1] + bb1, 0.f);
                float hB0 = fmaxf(acc[mt][nt][2] + bb0, 0.f);
                float hB1 = fmaxf(acc[mt][nt][3] + bb1, 0.f);
                p0[mt][0] = fmaf(hA0, w00, fmaf(hA1, w01, p0[mt][0]));
                p1[mt][0] = fmaf(hA0, w10, fmaf(hA1, w11, p1[mt][0]));
                p0[mt][1] = fmaf(hB0, w00, fmaf(hB1, w01, p0[mt][1]));
                p1[mt][1] = fmaf(hB0, w10, fmaf(hB1, w11, p1[mt][1]));
            }
        }
#pragma unroll
        for (int mt = 0; mt < 4; mt++) {
#pragma unroll
            for (int h = 0; h < 2; h++) {
                p0[mt][h] += __shfl_xor_sync(0xffffffffu, p0[mt][h], 1);
                p0[mt][h] += __shfl_xor_sync(0xffffffffu, p0[mt][h], 2);
                p1[mt][h] += __shfl_xor_sync(0xffffffffu, p1[mt][h], 1);
                p1[mt][h] += __shfl_xor_sync(0xffffffffu, p1[mt][h], 2);
            }
        }
        if (lr == 0) {
#pragma unroll
            for (int mt = 0; mt < 4; mt++) {
                const int rl = warp_m * 64 + mt * 16 + lq;
                red[(rl * 2 + warp_n) * 2 + 0]       = p0[mt][0];
                red[(rl * 2 + warp_n) * 2 + 1]       = p1[mt][0];
                red[((rl + 8) * 2 + warp_n) * 2 + 0] = p0[mt][1];
                red[((rl + 8) * 2 + warp_n) * 2 + 1] = p1[mt][1];
            }
        }
    } else if (warp_n == 2 && lr == 0) {
#pragma unroll
        for (int mt = 0; mt < 4; mt++) {
            const int rA = row0 + warp_m * 64 + mt * 16 + lq;
            g_xb1[rA]     = acc[mt][0][0];
            g_xb2[rA]     = acc[mt][0][1];
            g_xb1[rA + 8] = acc[mt][0][2];
            g_xb2[rA + 8] = acc[mt][0][3];
        }
    }
    __syncthreads();

    if (tid < 128) {
        float l0 = red[(tid * 2 + 0) * 2 + 0] + red[(tid * 2 + 1) * 2 + 0] + __ldg(&bc2[0]);
        float l1 = red[(tid * 2 + 0) * 2 + 1] + red[(tid * 2 + 1) * 2 + 1] + __ldg(&bc2[1]);
        float s0 = 1.f / (1.f + expf(-l0));
        float s1 = 1.f / (1.f + expf(-l1));
        g_sig[row0 + tid] = make_float2(s0, s1);
    }
}

// ======================= fp16 mma.sync GEMM (exact R15) ===================
// CTA tile 128x128, 4 warps of 64x64, 128 threads, K-chunk 64,
// 3-stage cp.async pipeline, 2 CTAs/SM.  Main loop fully unrolled.
#define STAGE_BYTES 32768
#define SMEM_BYTES  (3 * STAGE_BYTES)     // 98304

__global__ __launch_bounds__(128, 2) void gemm_tc_kernel(float* __restrict__ out)
{
    extern __shared__ char smem[];
    const uint32_t sbase = smem_u32(smem);
    const int tid   = threadIdx.x;
    const int wid   = tid >> 5;               // 0..3
    const int lane  = tid & 31;
    const int bx    = blockIdx.x;             // 0..11
    const int row0  = blockIdx.y * 128;
    const int colbase = bx * 128;

    const int warp_m = wid & 1;               // 2 row groups of 64
    const int warp_n = wid >> 1;              // 2 col groups of 64
    const int lq  = lane >> 2;
    const int lr  = lane & 3;
    const int t8  = lane >> 3;
    const int r8  = lane & 7;

    const int a_swz[4] = {
        warp_m * 64 + 0 * 16 + ((t8 & 1) << 3) + r8,
        warp_m * 64 + 1 * 16 + ((t8 & 1) << 3) + r8,
        warp_m * 64 + 2 * 16 + ((t8 & 1) << 3) + r8,
        warp_m * 64 + 3 * 16 + ((t8 & 1) << 3) + r8 };
    const int b_swz[4] = {
        warp_n * 64 + 0 * 16 + ((t8 >> 1) << 3) + r8,
        warp_n * 64 + 1 * 16 + ((t8 >> 1) << 3) + r8,
        warp_n * 64 + 2 * 16 + ((t8 >> 1) << 3) + r8,
        warp_n * 64 + 3 * 16 + ((t8 >> 1) << 3) + r8 };

    int ld_row[8], ld_c[8];
    uint32_t ld_dst[8];
#pragma unroll
    for (int i = 0; i < 8; i++) {
        int lin = tid + i * 128;
        ld_row[i] = lin >> 3;
        ld_c[i]   = lin & 7;
        ld_dst[i] = ld_row[i] * 128 + ((ld_c[i] ^ (ld_row[i] & 7)) << 4);
    }

    auto load_chunk = [&](int stage, int k0) {
        uint32_t ab = sbase + stage * STAGE_BYTES;
        uint32_t bb = ab + 16384;
#pragma unroll
        for (int i = 0; i < 8; i++) {
            const __half* src = g_X + (size_t)(row0 + ld_row[i]) * KDIM + k0 + ld_c[i] * 8;
            CP_ASYNC16(ab + ld_dst[i], src);
        }
#pragma unroll
        for (int i = 0; i < 8; i++) {
            const __half* src = g_Bh + (size_t)(colbase + ld_row[i]) * KDIM + k0 + ld_c[i] * 8;
            CP_ASYNC16(bb + ld_dst[i], src);
        }
    };

    float acc[4][8][4];
#pragma unroll
    for (int mt = 0; mt < 4; mt++)
#pragma unroll
        for (int nt = 0; nt < 8; nt++)
#pragma unroll
            for (int i = 0; i < 4; i++) acc[mt][nt][i] = 0.f;

    load_chunk(0, 0);  CP_COMMIT();
    load_chunk(1, 64); CP_COMMIT();

#pragma unroll
    for (int ch = 0; ch < 8; ch++) {
        const int stage = ch % 3;
        if (ch + 2 < 8) { load_chunk((ch + 2) % 3, (ch + 2) * 64); CP_COMMIT(); }
        if (ch < 6)       CP_WAIT(2);
        else if (ch == 6) CP_WAIT(1);
        else              CP_WAIT(0);
        __syncthreads();

        const uint32_t ab = sbase + stage * STAGE_BYTES;
        const uint32_t bb = ab + 16384;

#pragma unroll
        for (int kk = 0; kk < 4; kk++) {
            uint32_t af[4][4];
#pragma unroll
            for (int mt = 0; mt < 4; mt++) {
                int ac = kk * 2 + (t8 >> 1);
                uint32_t addr = ab + a_swz[mt] * 128 + ((ac ^ (a_swz[mt] & 7)) << 4);
                ldmatrix_x4(af[mt][0], af[mt][1], af[mt][2], af[mt][3], addr);
            }
            uint32_t bf[8][2];
#pragma unroll
            for (int nt2 = 0; nt2 < 4; nt2++) {
                int bc = kk * 2 + (t8 & 1);
                uint32_t addr = bb + b_swz[nt2] * 128 + ((bc ^ (b_swz[nt2] & 7)) << 4);
                ldmatrix_x4(bf[nt2 * 2][0], bf[nt2 * 2][1],
                            bf[nt2 * 2 + 1][0], bf[nt2 * 2 + 1][1], addr);
            }
#pragma unroll
            for (int mt = 0; mt < 4; mt++)
#pragma unroll
                for (int nt = 0; nt < 8; nt++)
                    mma_f16(acc[mt][nt], af[mt], bf[nt]);
        }
        __syncthreads();
    }

    // =================== fused epilogue ===================================
    if (bx < 4) {
        // interleaved W1/W2: actor col = warp_n*32 + nt*4 + lr
#pragma unroll
        for (int mt = 0; mt < 4; mt++) {
            const int rA = row0 + warp_m * 64 + mt * 16 + lq;
            const float2 sA = __ldg(&g_sig[rA]);
            const float2 sB = __ldg(&g_sig[rA + 8]);
#pragma unroll
            for (int nt = 0; nt < 8; nt++) {
                const int col = bx * 64 + warp_n * 32 + nt * 4 + lr;
                out[(size_t)rA * OUTA + col] =
                    fmaf(sA.x, acc[mt][nt][0], sA.y * acc[mt][nt][1]);
                out[(size_t)(rA + 8) * OUTA + col] =
                    fmaf(sB.x, acc[mt][nt][2], sB.y * acc[mt][nt][3]);
            }
        }
    } else {
        // quadratic tiles: fused row-dot with fp16 x
        const int qt = bx - 4;                          // 0..7
        const int jbase = (qt < 4 ? qt : qt - 4) * 128;
        float p[4][2];
#pragma unroll
        for (int mt = 0; mt < 4; mt++) { p[mt][0] = 0.f; p[mt][1] = 0.f; }
#pragma unroll
        for (int mt = 0; mt < 4; mt++) {
            const int rA = row0 + warp_m * 64 + mt * 16 + lq;
#pragma unroll
            for (int nt = 0; nt < 8; nt++) {
                const int j = jbase + warp_n * 64 + nt * 8 + 2 * lr;
                const __half2 h0 = __ldg((const __half2*)(g_X + (size_t)rA * KDIM + j));
                const __half2 h1 = __ldg((const __half2*)(g_X + (size_t)(rA + 8) * KDIM + j));
                const float2 x0 = __half22float2(h0);
                const float2 x1 = __half22float2(h1);
                p[mt][0] = fmaf(acc[mt][nt][0], x0.x, fmaf(acc[mt][nt][1], x0.y, p[mt][0]));
                p[mt][1] = fmaf(acc[mt][nt][2], x1.x, fmaf(acc[mt][nt][3], x1.y, p[mt][1]));
            }
        }
#pragma unroll
        for (int mt = 0; mt < 4; mt++) {
#pragma unroll
            for (int h = 0; h < 2; h++) {
                p[mt][h] += __shfl_xor_sync(0xffffffffu, p[mt][h], 1);
                p[mt][h] += __shfl_xor_sync(0xffffffffu, p[mt][h], 2);
            }
        }
        __syncthreads();
        float* red = (float*)smem;                      // [128][2]
        if (lr == 0) {
#pragma unroll
            for (int mt = 0; mt < 4; mt++) {
                const int rl = warp_m * 64 + mt * 16 + lq;
                red[rl * 2 + warp_n]       = p[mt][0];
                red[(rl + 8) * 2 + warp_n] = p[mt][1];
            }
        }
        __syncthreads();
        g_qpart[qt][row0 + tid] = red[tid * 2] + red[tid * 2 + 1];
    }
}

// ======================= critic kernel ====================================
__global__ __launch_bounds__(256) void critic_kernel(
    const float* __restrict__ c1, const float* __restrict__ c2,
    float* __restrict__ out)
{
    const int r = blockIdx.x * 256 + threadIdx.x;
    float q1 = g_qpart[0][r] + g_qpart[1][r] + g_qpart[2][r] + g_qpart[3][r]
             + g_xb1[r] + c1[0];
    float q2 = g_qpart[4][r] + g_qpart[5][r] + g_qpart[6][r] + g_qpart[7][r]
             + g_xb2[r] + c2[0];
    float2 s = g_sig[r];
    out[(size_t)BATCH * OUTA + r] = s.x * q1 + s.y * q2;
}

// =========================================================================
extern "C" void kernel_launch(void* const* d_in, const int* in_sizes, int n_in,
                              void* d_out, int out_size)
{
    const float* x   = (const float*)d_in[0];
    const float* W1  = (const float*)d_in[1];
    const float* W2  = (const float*)d_in[2];
    const float* A1  = (const float*)d_in[3];
    const float* b1  = (const float*)d_in[4];
    const float* c1  = (const float*)d_in[5];
    const float* A2  = (const float*)d_in[6];
    const float* b2  = (const float*)d_in[7];
    const float* c2  = (const float*)d_in[8];
    const float* Wc1 = (const float*)d_in[9];
    const float* bc1 = (const float*)d_in[10];
    const float* Wc2 = (const float*)d_in[11];
    const float* bc2 = (const float*)d_in[12];
    float* out = (float*)d_out;

    cudaFuncSetAttribute(gemm_tc_kernel,
                         cudaFuncAttributeMaxDynamicSharedMemorySize, SMEM_BYTES);

    pack_b_kernel<<<((NB + 128) * KDIM + 511) / 512, 512>>>(W1, W2, Wc1, b1, b2, A1, A2);
    chooser_kernel<<<BATCH / 128, 256, CH_SMEM>>>(x, bc1, Wc2, bc2);
    gemm_tc_kernel<<<dim3(12, BATCH / 128), 128, SMEM_BYTES>>>(out);
    critic_kernel<<<BATCH / 256, 256>>>(c1, c2, out);
}